// round 13
// baseline (speedup 1.0000x reference)
#include <cuda_runtime.h>
#include <cuda_bf16.h>
#include <math.h>

#define NN 768
#define XD 768
#define HID 300
#define HP 304
#define W1COLS 1536
#define NJB 24             // j blocks (768/32)
#define KSPLIT 4

typedef unsigned long long ull;

// Scratch (device globals -- no allocation allowed)
__device__ float g_gpx[KSPLIT][HP * NN];
__device__ float g_gpy[KSPLIT][HP * NN];
__device__ float g_hxT[HP * NN];   // [h][n], pad rows zeroed
__device__ float g_hyT[HP * NN];
__device__ float g_aT[HP * NN];    // [h][i] a = hy[perm i][h] + b1[h] (plain)
__device__ ull   g_cdup[HP * NN];  // [h][j] {c,c} dup of hxT
__device__ ull   g_w2dup[HP];      // {w,w}, 0 pad
__device__ float g_Ai[NN];
__device__ float g_Cj[NN];
__device__ float g_t0[NN];
__device__ float g_pm[NJB][NN];
__device__ float g_ps[NJB][NN];
__device__ float g_lse[NN];

__device__ __forceinline__ ull add_f32x2(ull a, ull b) {
    ull d; asm("add.rn.f32x2 %0, %1, %2;" : "=l"(d) : "l"(a), "l"(b)); return d;
}
__device__ __forceinline__ ull fma_f32x2(ull a, ull b, ull c) {
    ull d; asm("fma.rn.f32x2 %0, %1, %2, %3;" : "=l"(d) : "l"(a), "l"(b), "l"(c)); return d;
}
__device__ __forceinline__ ull dup_f32(float f) {
    ull d; unsigned u = __float_as_uint(f);
    asm("mov.b64 %0, {%1, %2};" : "=l"(d) : "r"(u), "r"(u)); return d;
}
__device__ __forceinline__ float lo_f(ull v) { return __uint_as_float((unsigned)(v & 0xffffffffu)); }
__device__ __forceinline__ float hi_f(ull v) { return __uint_as_float((unsigned)(v >> 32)); }
__device__ __forceinline__ float softplus_f(float z) {
    return fmaxf(z, 0.f) + log1pf(expf(-fabsf(z)));
}
__device__ __forceinline__ void cp16(unsigned s, const void* g) {
    asm volatile("cp.async.ca.shared.global [%0], [%1], 16;" :: "r"(s), "l"(g) : "memory");
}
__device__ __forceinline__ void cp_commit() {
    asm volatile("cp.async.commit_group;" ::: "memory");
}
template<int N> __device__ __forceinline__ void cp_wait() {
    asm volatile("cp.async.wait_group %0;" :: "n"(N) : "memory");
}

// ---------------------------------------------------------------------------
// GEMM split-K=4: partial[ks][h][n] = sum_{k in quarter ks} S[n][k]*W1[h][k+wofs]
// 64 thr, 64n x 64h tile, 8x8 micro. grid (12, 5, 8): z = which*4 + ks.
// ---------------------------------------------------------------------------
__global__ void __launch_bounds__(64) gemm_split(const float* __restrict__ x,
                                                 const float* __restrict__ y,
                                                 const float* __restrict__ W1) {
    __shared__ float sS[32][68];
    __shared__ float sW[32][68];

    const int which = blockIdx.z >> 2;
    const int ks = blockIdx.z & 3;
    const float* S = which ? y : x;
    const int wofs = which ? XD : 0;
    float* gp = which ? &g_gpy[ks][0] : &g_gpx[ks][0];

    const int n0 = blockIdx.x * 64;
    const int h0 = blockIdx.y * 64;
    const int t  = threadIdx.x;
    const int tx = t & 7;
    const int ty = t >> 3;
    const int kstart = ks * 192;     // 768/4
    const int hrow = h0 + t;
    const bool wok = hrow < HID;
    const float* Srow = &S[(size_t)(n0 + t) * XD + kstart];
    const float* Wrow = &W1[(size_t)(wok ? hrow : 0) * W1COLS + wofs + kstart];

    float4 rs[8], rw[8];
    const float4 z4 = make_float4(0.f, 0.f, 0.f, 0.f);
    #pragma unroll
    for (int g = 0; g < 8; g++) {
        rs[g] = *(const float4*)&Srow[g * 4];
        rw[g] = wok ? *(const float4*)&Wrow[g * 4] : z4;
    }

    ull acc[8][4] = {};

    for (int ci = 0; ci < 6; ci++) {     // 192/32
        __syncthreads();
        #pragma unroll
        for (int g = 0; g < 8; g++) {
            sS[g * 4 + 0][t] = rs[g].x; sS[g * 4 + 1][t] = rs[g].y;
            sS[g * 4 + 2][t] = rs[g].z; sS[g * 4 + 3][t] = rs[g].w;
            sW[g * 4 + 0][t] = rw[g].x; sW[g * 4 + 1][t] = rw[g].y;
            sW[g * 4 + 2][t] = rw[g].z; sW[g * 4 + 3][t] = rw[g].w;
        }
        __syncthreads();
        if (ci < 5) {
            const int kb = (ci + 1) * 32;
            #pragma unroll
            for (int g = 0; g < 8; g++) {
                rs[g] = *(const float4*)&Srow[kb + g * 4];
                rw[g] = wok ? *(const float4*)&Wrow[kb + g * 4] : z4;
            }
        }
        #pragma unroll
        for (int kk = 0; kk < 32; kk++) {
            float4 ha = *(const float4*)&sW[kk][ty * 8];
            float4 hb = *(const float4*)&sW[kk][ty * 8 + 4];
            ulonglong2 b01 = *(const ulonglong2*)&sS[kk][tx * 8];
            ulonglong2 b23 = *(const ulonglong2*)&sS[kk][tx * 8 + 4];
            float hv[8] = {ha.x, ha.y, ha.z, ha.w, hb.x, hb.y, hb.z, hb.w};
            ull bp[4] = {b01.x, b01.y, b23.x, b23.y};
            #pragma unroll
            for (int g = 0; g < 8; g++) {
                const ull wd = dup_f32(hv[g]);
                acc[g][0] = fma_f32x2(wd, bp[0], acc[g][0]);
                acc[g][1] = fma_f32x2(wd, bp[1], acc[g][1]);
                acc[g][2] = fma_f32x2(wd, bp[2], acc[g][2]);
                acc[g][3] = fma_f32x2(wd, bp[3], acc[g][3]);
            }
        }
    }

    #pragma unroll
    for (int g = 0; g < 8; g++) {
        const int h = h0 + ty * 8 + g;
        if (h < HID) {
            float4 v0 = make_float4(lo_f(acc[g][0]), hi_f(acc[g][0]),
                                    lo_f(acc[g][1]), hi_f(acc[g][1]));
            float4 v1 = make_float4(lo_f(acc[g][2]), hi_f(acc[g][2]),
                                    lo_f(acc[g][3]), hi_f(acc[g][3]));
            *(float4*)&gp[(size_t)h * NN + n0 + tx * 8]     = v0;
            *(float4*)&gp[(size_t)h * NN + n0 + tx * 8 + 4] = v1;
        }
    }
}

// ---------------------------------------------------------------------------
// reduce: hxT/hyT = sum of 4 split-K partials; zero pad rows; builds w2dup
// (covered by blocks 0 and 1: HP=304 > 256 threads).
// ---------------------------------------------------------------------------
__global__ void reduce_kernel(const float* __restrict__ W2) {
    const int m = blockIdx.y;
    const int idx4 = blockIdx.x * 256 + threadIdx.x;
    const int h = idx4 / (NN / 4);
    const int i = (idx4 - h * (NN / 4)) * 4;
    float* outT = m ? g_hyT : g_hxT;

    float4 v = make_float4(0.f, 0.f, 0.f, 0.f);
    if (h < HID) {
        #pragma unroll
        for (int ksp = 0; ksp < KSPLIT; ksp++) {
            const float* p = m ? &g_gpy[ksp][0] : &g_gpx[ksp][0];
            float4 a = *(const float4*)&p[(size_t)h * NN + i];
            v.x += a.x; v.y += a.y; v.z += a.z; v.w += a.w;
        }
    }
    *(float4*)&outT[(size_t)h * NN + i] = v;

    if (m == 0 && blockIdx.x < 2) {
        const int wi = blockIdx.x * 256 + threadIdx.x;
        if (wi < HP) {
            float w = (wi < HID) ? W2[wi] : 0.f;
            unsigned u = __float_as_uint(w);
            g_w2dup[wi] = ((ull)u << 32) | (ull)u;
        }
    }
}

// ---------------------------------------------------------------------------
// mid: blocks 0..227 -> g_aT (plain) + g_cdup (dup'ed hxT); 228..299 -> stats.
// ---------------------------------------------------------------------------
__global__ void mid_kernel(const int* __restrict__ perm,
                           const float* __restrict__ b1,
                           const float* __restrict__ W2,
                           const float* __restrict__ b2) {
    __shared__ float red[8][33];
    const int b = blockIdx.x;
    const int t = threadIdx.x;

    if (b < 228) {
        const int idx4 = b * 256 + t;
        const int h = idx4 / (NN / 4);
        const int i = (idx4 - h * (NN / 4)) * 4;
        float4 a = make_float4(0.f, 0.f, 0.f, 0.f);
        float4 c = a;
        if (h < HID) {
            const int4 pi = *(const int4*)&perm[i];
            const float* row = &g_hyT[(size_t)h * NN];
            const float bh = b1[h];
            a.x = row[pi.x] + bh; a.y = row[pi.y] + bh;
            a.z = row[pi.z] + bh; a.w = row[pi.w] + bh;
            c = *(const float4*)&g_hxT[(size_t)h * NN + i];
        }
        *(float4*)&g_aT[(size_t)h * NN + i] = a;
        ulonglong2 d0, d1;
        d0.x = dup_f32(c.x); d0.y = dup_f32(c.y);
        d1.x = dup_f32(c.z); d1.y = dup_f32(c.w);
        *(ulonglong2*)&g_cdup[(size_t)h * NN + i]     = d0;
        *(ulonglong2*)&g_cdup[(size_t)h * NN + i + 2] = d1;
        return;
    }

    const int bs = b - 228;
    const int mode = bs / 24;
    const int tx = t & 31, ty = t >> 5;
    const int n = (bs % 24) * 32 + tx;

    float p = 0.f;
    if (mode == 0) {
        for (int h = ty; h < HID; h += 8) {
            float v = g_hxT[(size_t)h * NN + n] + g_hyT[(size_t)h * NN + n] + b1[h];
            p = fmaf(W2[h], fmaxf(v, 0.f), p);
        }
    } else if (mode == 1) {
        const int pi = perm[n];
        for (int h = ty; h < HID; h += 8)
            p = fmaf(W2[h], g_hyT[(size_t)h * NN + pi] + b1[h], p);
    } else {
        for (int h = ty; h < HID; h += 8)
            p = fmaf(W2[h], g_hxT[(size_t)h * NN + n], p);
    }
    red[ty][tx] = p;
    __syncthreads();
    if (ty == 0) {
        float s = red[0][tx];
        #pragma unroll
        for (int k = 1; k < 8; k++) s += red[k][tx];
        if (mode == 0)      g_t0[n] = softplus_f(s + b2[0]);
        else if (mode == 1) g_Ai[n] = s;
        else                g_Cj[n] = s;
    }
}

// ---------------------------------------------------------------------------
// Pair v7: 32x32 tile, 256 thr, 576 CTAs (4/SM -> 32 warps/SM), 2i x 2j micro.
// i-pairs packed free from plain aT (LDS.64); j dups free from g_cdup (LDS.128).
// cp.async double-buffered. Fused per-(row, jblock) LSE partials.
// ---------------------------------------------------------------------------
__global__ void __launch_bounds__(256, 4) pair_kernel(const float* __restrict__ b2) {
    __shared__ float sA[2][16][32];     // plain a, 2KB/buf
    __shared__ ull   sC2[2][16][32];    // dup'ed c, 4KB/buf
    __shared__ ull   sw2[HP];

    const int t  = threadIdx.x;
    const int tx = t & 15;      // j-pair
    const int ty = t >> 4;      // i-pair
    const int i0 = blockIdx.y * 32;
    const int j0 = blockIdx.x * 32;

    for (int h = t; h < HP; h += 256) sw2[h] = g_w2dup[h];

    // prefetch chunk 0
    {
        if (t < 128) {
            const int r = t >> 3, c = (t & 7) * 4;
            cp16((unsigned)__cvta_generic_to_shared(&sA[0][r][c]),
                 &g_aT[(size_t)r * NN + i0 + c]);
        }
        const int r = t >> 4, cu = (t & 15) * 2;
        cp16((unsigned)__cvta_generic_to_shared(&sC2[0][r][cu]),
             &g_cdup[(size_t)r * NN + j0 + cu]);
        cp_commit();
    }
    __syncthreads();    // sw2 visible

    ull acc[2] = {};    // [j] packed over i-pair

    for (int ch = 0; ch < 19; ch++) {
        const int buf = ch & 1;
        if (ch + 1 < 19) {
            const int h1 = (ch + 1) * 16;
            if (t < 128) {
                const int r = t >> 3, c = (t & 7) * 4;
                cp16((unsigned)__cvta_generic_to_shared(&sA[buf ^ 1][r][c]),
                     &g_aT[(size_t)(h1 + r) * NN + i0 + c]);
            }
            const int r = t >> 4, cu = (t & 15) * 2;
            cp16((unsigned)__cvta_generic_to_shared(&sC2[buf ^ 1][r][cu]),
                 &g_cdup[(size_t)(h1 + r) * NN + j0 + cu]);
            cp_commit();
            cp_wait<1>();
        } else {
            cp_wait<0>();
        }
        __syncthreads();

        const int h0 = ch * 16;
        #pragma unroll
        for (int hh = 0; hh < 16; hh++) {
            const ull wv = sw2[h0 + hh];
            ull ap; asm("ld.shared.b64 %0, [%1];" : "=l"(ap)
                        : "r"((unsigned)__cvta_generic_to_shared(&sA[buf][hh][ty * 2])));
            ulonglong2 cd = *(const ulonglong2*)&sC2[buf][hh][tx * 2];
            ull v0 = add_f32x2(ap, cd.x) & 0x7FFFFFFF7FFFFFFFULL;
            ull v1 = add_f32x2(ap, cd.y) & 0x7FFFFFFF7FFFFFFFULL;
            acc[0] = fma_f32x2(wv, v0, acc[0]);
            acc[1] = fma_f32x2(wv, v1, acc[1]);
        }
        __syncthreads();
    }

    // epilogue: softplus + per-row LSE partials over this 32-j block
    const float bb = b2[0];
    float2 ai = *(const float2*)&g_Ai[i0 + ty * 2];
    float2 cj = *(const float2*)&g_Cj[j0 + tx * 2];

    // rows: lo = i0+ty*2, hi = i0+ty*2+1; cols j0+tx*2, j0+tx*2+1
    float v00 = softplus_f(fmaf(0.5f, lo_f(acc[0]) + ai.x + cj.x, bb));
    float v10 = softplus_f(fmaf(0.5f, hi_f(acc[0]) + ai.y + cj.x, bb));
    float v01 = softplus_f(fmaf(0.5f, lo_f(acc[1]) + ai.x + cj.y, bb));
    float v11 = softplus_f(fmaf(0.5f, hi_f(acc[1]) + ai.y + cj.y, bb));

    float mlo = fmaxf(v00, v01);
    float mhi = fmaxf(v10, v11);
    #pragma unroll
    for (int o = 1; o < 16; o <<= 1) {
        mlo = fmaxf(mlo, __shfl_xor_sync(0xffffffffu, mlo, o));
        mhi = fmaxf(mhi, __shfl_xor_sync(0xffffffffu, mhi, o));
    }
    float slo = expf(v00 - mlo) + expf(v01 - mlo);
    float shi = expf(v10 - mhi) + expf(v11 - mhi);
    #pragma unroll
    for (int o = 1; o < 16; o <<= 1) {
        slo += __shfl_xor_sync(0xffffffffu, slo, o);
        shi += __shfl_xor_sync(0xffffffffu, shi, o);
    }
    if (tx == 0) {
        g_pm[blockIdx.x][i0 + ty * 2]     = mlo;
        g_ps[blockIdx.x][i0 + ty * 2]     = slo;
        g_pm[blockIdx.x][i0 + ty * 2 + 1] = mhi;
        g_ps[blockIdx.x][i0 + ty * 2 + 1] = shi;
    }
}

// ---------------------------------------------------------------------------
// Parallel LSE merge + final reduce.
// ---------------------------------------------------------------------------
__global__ void lse_merge_kernel() {
    const int r = blockIdx.x * 128 + threadIdx.x;
    if (r >= NN) return;
    float m = -INFINITY;
    #pragma unroll
    for (int jb = 0; jb < NJB; jb++) m = fmaxf(m, g_pm[jb][r]);
    float s = 0.f;
    #pragma unroll
    for (int jb = 0; jb < NJB; jb++) s += g_ps[jb][r] * expf(g_pm[jb][r] - m);
    g_lse[r] = m + logf(s);
}

__global__ void final_kernel(float* __restrict__ out) {
    __shared__ float r0[256], r1[256];
    const int t = threadIdx.x;
    float s0 = 0.f, s1 = 0.f;
    for (int r = t; r < NN; r += 256) { s0 += g_t0[r]; s1 += g_lse[r]; }
    r0[t] = s0; r1[t] = s1; __syncthreads();
    for (int s = 128; s > 0; s >>= 1) {
        if (t < s) { r0[t] += r0[t + s]; r1[t] += r1[t + s]; }
        __syncthreads();
    }
    if (t == 0)
        out[0] = r0[0] / (float)NN - (r1[0] / (float)NN - logf((float)NN));
}

// ---------------------------------------------------------------------------
// Inputs: x_samples, y_samples, perm, W1, b1, W2, b2
// ---------------------------------------------------------------------------
extern "C" void kernel_launch(void* const* d_in, const int* in_sizes, int n_in,
                              void* d_out, int out_size) {
    const float* x    = (const float*)d_in[0];
    const float* y    = (const float*)d_in[1];
    const int*   perm = (const int*)d_in[2];
    const float* W1   = (const float*)d_in[3];
    const float* b1   = (const float*)d_in[4];
    const float* W2   = (const float*)d_in[5];
    const float* b2   = (const float*)d_in[6];
    float* out = (float*)d_out;

    gemm_split<<<dim3(NN / 64, 5, 8), 64>>>(x, y, W1);          // idx 0
    reduce_kernel<<<dim3(228, 2), 256>>>(W2);                   // idx 1
    mid_kernel<<<300, 256>>>(perm, b1, W2, b2);                 // idx 2
    pair_kernel<<<dim3(NN / 32, NN / 32), 256>>>(b2);           // idx 3 (profiled)
    lse_merge_kernel<<<6, 128>>>();                             // idx 4
    final_kernel<<<1, 256>>>(out);                              // idx 5
}

// round 15
// speedup vs baseline: 1.2721x; 1.2721x over previous
#include <cuda_runtime.h>
#include <cuda_bf16.h>
#include <math.h>

#define NN 768
#define XD 768
#define HID 300
#define HP 304
#define W1COLS 1536
#define NJB 12             // j blocks (768/64)
#define KSPLIT 2

typedef unsigned long long ull;

// Scratch (device globals -- no allocation allowed)
__device__ float g_gpx[KSPLIT][HP * NN];
__device__ float g_gpy[KSPLIT][HP * NN];
__device__ float g_hxT[HP * NN];   // [h][n], pad rows zeroed by reduce
__device__ float g_hyT[HP * NN];
__device__ ull   g_adup[HP * NN];  // [h][i] {a,a}, a = hy[perm i][h] + b1[h]
__device__ ull   g_w2dup[HP];      // {w,w}, 0 pad
__device__ float g_Ai[NN];
__device__ float g_Cj[NN];
__device__ float g_t0[NN];
__device__ float g_pm[NJB][NN];
__device__ float g_ps[NJB][NN];

__device__ __forceinline__ ull add_f32x2(ull a, ull b) {
    ull d; asm("add.rn.f32x2 %0, %1, %2;" : "=l"(d) : "l"(a), "l"(b)); return d;
}
__device__ __forceinline__ ull fma_f32x2(ull a, ull b, ull c) {
    ull d; asm("fma.rn.f32x2 %0, %1, %2, %3;" : "=l"(d) : "l"(a), "l"(b), "l"(c)); return d;
}
__device__ __forceinline__ ull dup_f32(float f) {
    ull d; unsigned u = __float_as_uint(f);
    asm("mov.b64 %0, {%1, %2};" : "=l"(d) : "r"(u), "r"(u)); return d;
}
__device__ __forceinline__ float lo_f(ull v) { return __uint_as_float((unsigned)(v & 0xffffffffu)); }
__device__ __forceinline__ float hi_f(ull v) { return __uint_as_float((unsigned)(v >> 32)); }
__device__ __forceinline__ float softplus_f(float z) {
    return fmaxf(z, 0.f) + log1pf(expf(-fabsf(z)));
}
__device__ __forceinline__ void cp16(unsigned s, const void* g) {
    asm volatile("cp.async.ca.shared.global [%0], [%1], 16;" :: "r"(s), "l"(g) : "memory");
}
__device__ __forceinline__ void cp_commit() {
    asm volatile("cp.async.commit_group;" ::: "memory");
}
template<int N> __device__ __forceinline__ void cp_wait() {
    asm volatile("cp.async.wait_group %0;" :: "n"(N) : "memory");
}

// ---------------------------------------------------------------------------
// GEMM split-K=2: partial[ks][h][n] = sum_{half ks} S[n][k]*W1[h][k+wofs]
// 64 thr, 64n x 64h tile, 8x8 micro. grid (12, 5, 4): z = which*2 + ks.
// ---------------------------------------------------------------------------
__global__ void __launch_bounds__(64) gemm_split(const float* __restrict__ x,
                                                 const float* __restrict__ y,
                                                 const float* __restrict__ W1) {
    __shared__ float sS[32][68];
    __shared__ float sW[32][68];

    const int which = blockIdx.z >> 1;
    const int ks = blockIdx.z & 1;
    const float* S = which ? y : x;
    const int wofs = which ? XD : 0;
    float* gp = which ? &g_gpy[ks][0] : &g_gpx[ks][0];

    const int n0 = blockIdx.x * 64;
    const int h0 = blockIdx.y * 64;
    const int t  = threadIdx.x;
    const int tx = t & 7;
    const int ty = t >> 3;
    const int kstart = ks * 384;
    const int hrow = h0 + t;
    const bool wok = hrow < HID;
    const float* Srow = &S[(size_t)(n0 + t) * XD + kstart];
    const float* Wrow = &W1[(size_t)(wok ? hrow : 0) * W1COLS + wofs + kstart];

    float4 rs[8], rw[8];
    const float4 z4 = make_float4(0.f, 0.f, 0.f, 0.f);
    #pragma unroll
    for (int g = 0; g < 8; g++) {
        rs[g] = *(const float4*)&Srow[g * 4];
        rw[g] = wok ? *(const float4*)&Wrow[g * 4] : z4;
    }

    ull acc[8][4] = {};

    for (int ci = 0; ci < 12; ci++) {
        __syncthreads();
        #pragma unroll
        for (int g = 0; g < 8; g++) {
            sS[g * 4 + 0][t] = rs[g].x; sS[g * 4 + 1][t] = rs[g].y;
            sS[g * 4 + 2][t] = rs[g].z; sS[g * 4 + 3][t] = rs[g].w;
            sW[g * 4 + 0][t] = rw[g].x; sW[g * 4 + 1][t] = rw[g].y;
            sW[g * 4 + 2][t] = rw[g].z; sW[g * 4 + 3][t] = rw[g].w;
        }
        __syncthreads();
        if (ci < 11) {
            const int kb = (ci + 1) * 32;
            #pragma unroll
            for (int g = 0; g < 8; g++) {
                rs[g] = *(const float4*)&Srow[kb + g * 4];
                rw[g] = wok ? *(const float4*)&Wrow[kb + g * 4] : z4;
            }
        }
        #pragma unroll
        for (int kk = 0; kk < 32; kk++) {
            float4 ha = *(const float4*)&sW[kk][ty * 8];
            float4 hb = *(const float4*)&sW[kk][ty * 8 + 4];
            ulonglong2 b01 = *(const ulonglong2*)&sS[kk][tx * 8];
            ulonglong2 b23 = *(const ulonglong2*)&sS[kk][tx * 8 + 4];
            float hv[8] = {ha.x, ha.y, ha.z, ha.w, hb.x, hb.y, hb.z, hb.w};
            ull bp[4] = {b01.x, b01.y, b23.x, b23.y};
            #pragma unroll
            for (int g = 0; g < 8; g++) {
                const ull wd = dup_f32(hv[g]);
                acc[g][0] = fma_f32x2(wd, bp[0], acc[g][0]);
                acc[g][1] = fma_f32x2(wd, bp[1], acc[g][1]);
                acc[g][2] = fma_f32x2(wd, bp[2], acc[g][2]);
                acc[g][3] = fma_f32x2(wd, bp[3], acc[g][3]);
            }
        }
    }

    #pragma unroll
    for (int g = 0; g < 8; g++) {
        const int h = h0 + ty * 8 + g;
        if (h < HID) {
            float4 v0 = make_float4(lo_f(acc[g][0]), hi_f(acc[g][0]),
                                    lo_f(acc[g][1]), hi_f(acc[g][1]));
            float4 v1 = make_float4(lo_f(acc[g][2]), hi_f(acc[g][2]),
                                    lo_f(acc[g][3]), hi_f(acc[g][3]));
            *(float4*)&gp[(size_t)h * NN + n0 + tx * 8]     = v0;
            *(float4*)&gp[(size_t)h * NN + n0 + tx * 8 + 4] = v1;
        }
    }
}

// ---------------------------------------------------------------------------
// reduce: hxT/hyT = partial sums; zero pad rows; w2dup (blocks 0+1 cover HP).
// ---------------------------------------------------------------------------
__global__ void reduce_kernel(const float* __restrict__ W2) {
    const int m = blockIdx.y;
    const int idx4 = blockIdx.x * 256 + threadIdx.x;
    const int h = idx4 / (NN / 4);
    const int i = (idx4 - h * (NN / 4)) * 4;
    float* outT = m ? g_hyT : g_hxT;

    float4 v = make_float4(0.f, 0.f, 0.f, 0.f);
    if (h < HID) {
        #pragma unroll
        for (int ksp = 0; ksp < KSPLIT; ksp++) {
            const float* p = m ? &g_gpy[ksp][0] : &g_gpx[ksp][0];
            float4 a = *(const float4*)&p[(size_t)h * NN + i];
            v.x += a.x; v.y += a.y; v.z += a.z; v.w += a.w;
        }
    }
    *(float4*)&outT[(size_t)h * NN + i] = v;

    if (m == 0 && blockIdx.x < 2) {
        const int wi = blockIdx.x * 256 + threadIdx.x;
        if (wi < HP) {
            float w = (wi < HID) ? W2[wi] : 0.f;
            unsigned u = __float_as_uint(w);
            g_w2dup[wi] = ((ull)u << 32) | (ull)u;
        }
    }
}

// ---------------------------------------------------------------------------
// mid: blocks 0..227 -> g_adup; 228..299 -> stats (t0, Ai, Cj).
// ---------------------------------------------------------------------------
__global__ void mid_kernel(const int* __restrict__ perm,
                           const float* __restrict__ b1,
                           const float* __restrict__ W2,
                           const float* __restrict__ b2) {
    __shared__ float red[8][33];
    const int b = blockIdx.x;
    const int t = threadIdx.x;

    if (b < 228) {
        const int idx4 = b * 256 + t;
        const int h = idx4 / (NN / 4);
        const int i = (idx4 - h * (NN / 4)) * 4;
        float4 v = make_float4(0.f, 0.f, 0.f, 0.f);
        if (h < HID) {
            const int4 pi = *(const int4*)&perm[i];
            const float* row = &g_hyT[(size_t)h * NN];
            const float bh = b1[h];
            v.x = row[pi.x] + bh; v.y = row[pi.y] + bh;
            v.z = row[pi.z] + bh; v.w = row[pi.w] + bh;
        }
        ulonglong2 d0, d1;
        d0.x = dup_f32(v.x); d0.y = dup_f32(v.y);
        d1.x = dup_f32(v.z); d1.y = dup_f32(v.w);
        *(ulonglong2*)&g_adup[(size_t)h * NN + i]     = d0;
        *(ulonglong2*)&g_adup[(size_t)h * NN + i + 2] = d1;
        return;
    }

    const int bs = b - 228;
    const int mode = bs / 24;
    const int tx = t & 31, ty = t >> 5;
    const int n = (bs % 24) * 32 + tx;

    float p = 0.f;
    if (mode == 0) {
        for (int h = ty; h < HID; h += 8) {
            float v = g_hxT[(size_t)h * NN + n] + g_hyT[(size_t)h * NN + n] + b1[h];
            p = fmaf(W2[h], fmaxf(v, 0.f), p);
        }
    } else if (mode == 1) {
        const int pi = perm[n];
        for (int h = ty; h < HID; h += 8)
            p = fmaf(W2[h], g_hyT[(size_t)h * NN + pi] + b1[h], p);
    } else {
        for (int h = ty; h < HID; h += 8)
            p = fmaf(W2[h], g_hxT[(size_t)h * NN + n], p);
    }
    red[ty][tx] = p;
    __syncthreads();
    if (ty == 0) {
        float s = red[0][tx];
        #pragma unroll
        for (int k = 1; k < 8; k++) s += red[k][tx];
        if (mode == 0)      g_t0[n] = softplus_f(s + b2[0]);
        else if (mode == 1) g_Ai[n] = s;
        else                g_Cj[n] = s;
    }
}

// ---------------------------------------------------------------------------
// Pair v8: 32i x 64j tile, 288 CTAs (~2/SM), 256 thr = 2 h-groups x 128.
// dup-a + plain-c, 4i x 4j micro (2.25 issues / 3 B per triple),
// cp.async double-buffer, named barriers per group, fused LSE partials.
// ---------------------------------------------------------------------------
__global__ void __launch_bounds__(256, 2) pair_kernel(const float* __restrict__ b2) {
    __shared__ ull   sA2[2][2][16][32];   // [group][buf][h][i] dup'ed, 16KB
    __shared__ float sC[2][2][16][64];    // [group][buf][h][j] plain, 16KB
    __shared__ ull   sw2[HP];             // 2.4KB

    const int g  = threadIdx.y;          // 0 or 1
    const int t  = threadIdx.x;          // 0..127
    const int tx = t & 15;               // j quad (4j)
    const int ty = t >> 4;               // i quad 0..7 (4i)
    const int i0 = blockIdx.y * 32;
    const int j0 = blockIdx.x * 64;
    const int row  = t >> 3;             // loader row 0..15
    const int colu = (t & 7) * 4;        // a: ull col 0..28
    const int colf = (t & 7) * 8;        // c: float col 0..56

    for (int h = g * 128 + t; h < HP; h += 256) sw2[h] = g_w2dup[h];

    const int c0 = g ? 10 : 0;
    const int c1 = g ? 19 : 10;          // 19 chunks (HP=304)

    {
        const int h0 = c0 * 16;
        unsigned da = (unsigned)__cvta_generic_to_shared(&sA2[g][0][row][colu]);
        cp16(da,      &g_adup[(size_t)(h0 + row) * NN + i0 + colu]);
        cp16(da + 16, &g_adup[(size_t)(h0 + row) * NN + i0 + colu + 2]);
        unsigned dc = (unsigned)__cvta_generic_to_shared(&sC[g][0][row][colf]);
        cp16(dc,      &g_hxT[(size_t)(h0 + row) * NN + j0 + colf]);
        cp16(dc + 16, &g_hxT[(size_t)(h0 + row) * NN + j0 + colf + 4]);
        cp_commit();
    }
    __syncthreads();   // sw2 visible

    ull acc[4][2] = {};   // [i(p)][j-pair]

    for (int ch = c0; ch < c1; ch++) {
        const int buf = (ch - c0) & 1;
        if (ch + 1 < c1) {
            const int h1 = (ch + 1) * 16;
            unsigned da = (unsigned)__cvta_generic_to_shared(&sA2[g][buf ^ 1][row][colu]);
            cp16(da,      &g_adup[(size_t)(h1 + row) * NN + i0 + colu]);
            cp16(da + 16, &g_adup[(size_t)(h1 + row) * NN + i0 + colu + 2]);
            unsigned dc = (unsigned)__cvta_generic_to_shared(&sC[g][buf ^ 1][row][colf]);
            cp16(dc,      &g_hxT[(size_t)(h1 + row) * NN + j0 + colf]);
            cp16(dc + 16, &g_hxT[(size_t)(h1 + row) * NN + j0 + colf + 4]);
            cp_commit();
            cp_wait<1>();
        } else {
            cp_wait<0>();
        }
        asm volatile("bar.sync %0, 128;" :: "r"(g + 1) : "memory");

        const int h0 = ch * 16;
        #pragma unroll
        for (int hh = 0; hh < 16; hh++) {
            const ull wv = sw2[h0 + hh];
            ulonglong2 a01 = *(const ulonglong2*)&sA2[g][buf][hh][ty * 4];
            ulonglong2 a23 = *(const ulonglong2*)&sA2[g][buf][hh][ty * 4 + 2];
            ulonglong2 cp  = *(const ulonglong2*)&sC[g][buf][hh][tx * 4]; // j pairs
            ull a2[4] = {a01.x, a01.y, a23.x, a23.y};
            #pragma unroll
            for (int p = 0; p < 4; p++) {
                ull v0 = add_f32x2(a2[p], cp.x) & 0x7FFFFFFF7FFFFFFFULL;
                ull v1 = add_f32x2(a2[p], cp.y) & 0x7FFFFFFF7FFFFFFFULL;
                acc[p][0] = fma_f32x2(wv, v0, acc[p][0]);
                acc[p][1] = fma_f32x2(wv, v1, acc[p][1]);
            }
        }
        asm volatile("bar.sync %0, 128;" :: "r"(g + 1) : "memory");
    }

    // combine: g1 stores partials into its own (finished) tile region
    ull* cb = (ull*)&sA2[1][0][0][0];    // 8KB = 128 threads x 8 ull
    __syncthreads();
    if (g == 1) {
        #pragma unroll
        for (int p = 0; p < 4; p++) {
            cb[t * 8 + p * 2 + 0] = acc[p][0];
            cb[t * 8 + p * 2 + 1] = acc[p][1];
        }
    }
    __syncthreads();
    if (g == 0) {
        const float bb = b2[0];
        float cj[4], ai[4];
        *(float4*)cj = *(const float4*)&g_Cj[j0 + tx * 4];
        *(float4*)ai = *(const float4*)&g_Ai[i0 + ty * 4];

        #pragma unroll
        for (int p = 0; p < 4; p++) {
            acc[p][0] = add_f32x2(acc[p][0], cb[t * 8 + p * 2 + 0]);
            acc[p][1] = add_f32x2(acc[p][1], cb[t * 8 + p * 2 + 1]);
            float s[4] = {lo_f(acc[p][0]), hi_f(acc[p][0]),
                          lo_f(acc[p][1]), hi_f(acc[p][1])};
            float v[4];
            #pragma unroll
            for (int q = 0; q < 4; q++)
                v[q] = softplus_f(fmaf(0.5f, s[q] + ai[p] + cj[q], bb));

            // row-LSE partial over 64 j (16 lanes per row; xor<16 stays in row)
            float m = fmaxf(fmaxf(v[0], v[1]), fmaxf(v[2], v[3]));
            #pragma unroll
            for (int o = 1; o < 16; o <<= 1)
                m = fmaxf(m, __shfl_xor_sync(0xffffffffu, m, o));
            float sm = expf(v[0]-m) + expf(v[1]-m) + expf(v[2]-m) + expf(v[3]-m);
            #pragma unroll
            for (int o = 1; o < 16; o <<= 1)
                sm += __shfl_xor_sync(0xffffffffu, sm, o);
            if (tx == 0) {
                g_pm[blockIdx.x][i0 + ty * 4 + p] = m;
                g_ps[blockIdx.x][i0 + ty * 4 + p] = sm;
            }
        }
    }
}

// ---------------------------------------------------------------------------
// Fused tail: per-row LSE merge (768 threads) + block reduce -> scalar.
// FIX (R14 bug): power-of-two guarded tree (384-start tree dropped element 2
// at the 3->1 transition, losing 256 rows).
// ---------------------------------------------------------------------------
__global__ void tail_kernel(float* __restrict__ out) {
    __shared__ float r0[768], r1[768];
    const int t = threadIdx.x;   // 0..767

    float m = -INFINITY;
    #pragma unroll
    for (int jb = 0; jb < NJB; jb++) m = fmaxf(m, g_pm[jb][t]);
    float s = 0.f;
    #pragma unroll
    for (int jb = 0; jb < NJB; jb++) s += g_ps[jb][t] * expf(g_pm[jb][t] - m);
    r1[t] = m + logf(s);
    r0[t] = g_t0[t];
    __syncthreads();

    #pragma unroll
    for (int st = 512; st > 0; st >>= 1) {
        if (t < st && t + st < NN) { r0[t] += r0[t + st]; r1[t] += r1[t + st]; }
        __syncthreads();
    }
    if (t == 0)
        out[0] = r0[0] / (float)NN - (r1[0] / (float)NN - logf((float)NN));
}

// ---------------------------------------------------------------------------
// Inputs: x_samples, y_samples, perm, W1, b1, W2, b2
// ---------------------------------------------------------------------------
extern "C" void kernel_launch(void* const* d_in, const int* in_sizes, int n_in,
                              void* d_out, int out_size) {
    const float* x    = (const float*)d_in[0];
    const float* y    = (const float*)d_in[1];
    const int*   perm = (const int*)d_in[2];
    const float* W1   = (const float*)d_in[3];
    const float* b1   = (const float*)d_in[4];
    const float* W2   = (const float*)d_in[5];
    const float* b2   = (const float*)d_in[6];
    float* out = (float*)d_out;

    gemm_split<<<dim3(NN / 64, 5, 4), 64>>>(x, y, W1);              // idx 0
    reduce_kernel<<<dim3(228, 2), 256>>>(W2);                       // idx 1
    mid_kernel<<<300, 256>>>(perm, b1, W2, b2);                     // idx 2
    pair_kernel<<<dim3(NN / 64, NN / 32), dim3(128, 2)>>>(b2);      // idx 3 (profiled)
    tail_kernel<<<1, 768>>>(out);                                   // idx 4
}